// round 2
// baseline (speedup 1.0000x reference)
#include <cuda_runtime.h>
#include <math.h>

#define NB   64
#define NT   256
#define EMBD 512
#define RNN  1024
#define Z4   4096
#define HIDN 128
#define NLAB 4
#define GRID_R 128

#define BM 64
#define BN 128
#define BK 16

// ---------------- static device scratch ----------------------------------
__device__ float g_XW[(size_t)NT * NB * Z4];          // emb[x] @ W, [t][b][4096]
__device__ float g_Upk[(size_t)GRID_R * 32 * RNN];    // repacked U: [jb][c][k]
__device__ float g_h2[2][NB * RNN];                   // ping-pong h
__device__ float g_c[NB * RNN];
__device__ float g_pooled[NB * RNN];
__device__ int   g_active[NT];
__device__ unsigned g_arrive;
__device__ unsigned g_release;

// packed fp32x2 FMA (2x FFMA rate on sm_103a fma pipe)
__device__ __forceinline__ float2 ffma2(float2 a, float2 b, float2 c) {
    unsigned long long ra = reinterpret_cast<unsigned long long&>(a);
    unsigned long long rb = reinterpret_cast<unsigned long long&>(b);
    unsigned long long rc = reinterpret_cast<unsigned long long&>(c);
    unsigned long long rd;
    asm("fma.rn.f32x2 %0, %1, %2, %3;" : "=l"(rd) : "l"(ra), "l"(rb), "l"(rc));
    return reinterpret_cast<float2&>(rd);
}

__device__ __forceinline__ void cp_async16(void* smem_dst, const void* gsrc) {
    unsigned s = (unsigned)__cvta_generic_to_shared(smem_dst);
    asm volatile("cp.async.cg.shared.global [%0], [%1], 16;" :: "r"(s), "l"(gsrc));
}
#define CP_COMMIT() asm volatile("cp.async.commit_group;" ::: "memory")
#define CP_WAIT0()  asm volatile("cp.async.wait_group 0;" ::: "memory")

// software grid barrier (all GRID_R blocks co-resident: 1 block/SM, 128 <= 148 SMs)
__device__ __forceinline__ void gsync(unsigned target) {
    __threadfence();
    __syncthreads();
    if (threadIdx.x == 0) {
        unsigned prev = atomicAdd(&g_arrive, 1);
        if (prev == GRID_R - 1) {
            g_arrive = 0;
            asm volatile("st.release.gpu.global.u32 [%0], %1;" :: "l"(&g_release), "r"(target) : "memory");
        } else {
            unsigned v;
            do {
                asm volatile("ld.acquire.gpu.global.u32 %0, [%1];" : "=r"(v) : "l"(&g_release) : "memory");
            } while (v < target);
        }
    }
    __syncthreads();
    __threadfence();   // gpu-scope fence -> CCTL.IVALL: flush stale L1 lines of h
}

// ---------------- prep: active flags + barrier reset ----------------------
__global__ void prep_kernel(const int* __restrict__ x) {
    int t = threadIdx.x;
    if (t < NT) {
        int act = 0;
        for (int b = 0; b < NB; b++) act |= (x[b * NT + t] != 0);
        g_active[t] = act;
    }
    if (t == 0) { g_arrive = 0; g_release = 0; }
}

__global__ void zero_kernel() {
    int i = blockIdx.x * blockDim.x + threadIdx.x;
    if (i < NB * RNN) {
        g_h2[0][i] = 0.f; g_h2[1][i] = 0.f; g_c[i] = 0.f; g_pooled[i] = 0.f;
    }
}

// ---------------- repack U -> [jb][gate*8+jj][k] ---------------------------
__global__ void upack_kernel(const float* __restrict__ U) {
    int idx = blockIdx.x * 256 + threadIdx.x;   // 0 .. 4M-1
    int k = idx >> 12;
    int n = idx & 4095;
    int gate = n >> 10;
    int cj = n & 1023;
    int jb = cj >> 3;
    int jj = cj & 7;
    g_Upk[(((size_t)jb * 32) + (gate * 8 + jj)) * RNN + k] = U[idx];
}

// ---------------- XW = emb[x] @ W (unchanged, early-exit on inactive t) ---
__global__ __launch_bounds__(128) void xw_kernel(const int* __restrict__ x,
                                                 const float* __restrict__ emb,
                                                 const float* __restrict__ W) {
    const int t = blockIdx.y;
    if (!g_active[t]) return;
    const int n0 = blockIdx.x * BN;

    __shared__ float As[2][BK][BM];
    __shared__ float Bs[2][BK][BN];
    __shared__ int idxs[NB];

    const int tid = threadIdx.x;
    if (tid < NB) idxs[tid] = x[tid * NT + t];
    __syncthreads();

    const int am   = tid >> 2;
    const int ak   = (tid & 3) << 2;
    const int brow = tid >> 5;
    const int bcol = (tid & 31) << 2;
    const int tb = tid >> 4;
    const int tc = tid & 15;
    const int m0 = tb * 8;
    const int c0 = tc * 8;

    const size_t eA0 = (size_t)idxs[am] * EMBD;
    const size_t eA1 = (size_t)idxs[am + 32] * EMBD;

    float2 acc[8][4];
    #pragma unroll
    for (int i = 0; i < 8; i++)
        #pragma unroll
        for (int j = 0; j < 4; j++) acc[i][j] = make_float2(0.f, 0.f);

    float4 ra0, ra1, rb[4];

    ra0 = *reinterpret_cast<const float4*>(emb + eA0 + ak);
    ra1 = *reinterpret_cast<const float4*>(emb + eA1 + ak);
    #pragma unroll
    for (int j = 0; j < 4; j++)
        rb[j] = *reinterpret_cast<const float4*>(W + (size_t)(brow + 4 * j) * Z4 + n0 + bcol);
    As[0][ak + 0][am] = ra0.x; As[0][ak + 1][am] = ra0.y;
    As[0][ak + 2][am] = ra0.z; As[0][ak + 3][am] = ra0.w;
    As[0][ak + 0][am + 32] = ra1.x; As[0][ak + 1][am + 32] = ra1.y;
    As[0][ak + 2][am + 32] = ra1.z; As[0][ak + 3][am + 32] = ra1.w;
    #pragma unroll
    for (int j = 0; j < 4; j++)
        *reinterpret_cast<float4*>(&Bs[0][brow + 4 * j][bcol]) = rb[j];
    __syncthreads();

    const int nch = EMBD / BK;
    for (int ch = 0; ch < nch; ch++) {
        const int buf = ch & 1;
        if (ch + 1 < nch) {
            const int k0 = (ch + 1) * BK;
            ra0 = *reinterpret_cast<const float4*>(emb + eA0 + k0 + ak);
            ra1 = *reinterpret_cast<const float4*>(emb + eA1 + k0 + ak);
            #pragma unroll
            for (int j = 0; j < 4; j++)
                rb[j] = *reinterpret_cast<const float4*>(W + (size_t)(k0 + brow + 4 * j) * Z4 + n0 + bcol);
        }
        #pragma unroll
        for (int kk = 0; kk < BK; kk++) {
            const float4 a0 = *reinterpret_cast<const float4*>(&As[buf][kk][m0]);
            const float4 a1 = *reinterpret_cast<const float4*>(&As[buf][kk][m0 + 4]);
            const float4 b0 = *reinterpret_cast<const float4*>(&Bs[buf][kk][c0]);
            const float4 b1 = *reinterpret_cast<const float4*>(&Bs[buf][kk][c0 + 4]);
            float2 bv[4];
            bv[0] = make_float2(b0.x, b0.y); bv[1] = make_float2(b0.z, b0.w);
            bv[2] = make_float2(b1.x, b1.y); bv[3] = make_float2(b1.z, b1.w);
            const float av[8] = {a0.x, a0.y, a0.z, a0.w, a1.x, a1.y, a1.z, a1.w};
            #pragma unroll
            for (int i = 0; i < 8; i++) {
                const float2 as = make_float2(av[i], av[i]);
                #pragma unroll
                for (int j = 0; j < 4; j++) acc[i][j] = ffma2(as, bv[j], acc[i][j]);
            }
        }
        if (ch + 1 < nch) {
            const int nb = (ch + 1) & 1;
            As[nb][ak + 0][am] = ra0.x; As[nb][ak + 1][am] = ra0.y;
            As[nb][ak + 2][am] = ra0.z; As[nb][ak + 3][am] = ra0.w;
            As[nb][ak + 0][am + 32] = ra1.x; As[nb][ak + 1][am + 32] = ra1.y;
            As[nb][ak + 2][am + 32] = ra1.z; As[nb][ak + 3][am + 32] = ra1.w;
            #pragma unroll
            for (int j = 0; j < 4; j++)
                *reinterpret_cast<float4*>(&Bs[nb][brow + 4 * j][bcol]) = rb[j];
        }
        __syncthreads();
    }

    float* C = g_XW + (size_t)t * NB * Z4;
    #pragma unroll
    for (int i = 0; i < 8; i++) {
        const int row = m0 + i;
        float4 v0 = make_float4(acc[i][0].x, acc[i][0].y, acc[i][1].x, acc[i][1].y);
        float4 v1 = make_float4(acc[i][2].x, acc[i][2].y, acc[i][3].x, acc[i][3].y);
        *reinterpret_cast<float4*>(C + (size_t)row * Z4 + n0 + c0) = v0;
        *reinterpret_cast<float4*>(C + (size_t)row * Z4 + n0 + c0 + 4) = v1;
    }
}

// ---------------- persistent fused recurrence ------------------------------
// 128 blocks x 256 threads; block owns 8 hidden units (all 4 gates), all 64 b.
// smem: UsT[32][1028] + hbuf[2][64][132] + zbuf[64][33]f2 + sact[256]
#define SM_UST   (32 * 1028)
#define SM_HBUF  (64 * 132)
#define SM_ZOFF  (SM_UST + 2 * SM_HBUF)
#define SM_ZF2   (64 * 33)
#define SMEM_RNN ((SM_ZOFF + 2 * SM_ZF2 + 256) * 4)

__global__ __launch_bounds__(256, 1) void rnn_kernel(const int* __restrict__ x,
                                                     const float* __restrict__ bias) {
    extern __shared__ float sm[];
    float*  UsT  = sm;
    float*  hb0  = sm + SM_UST;
    float*  hb1  = hb0 + SM_HBUF;
    float2* zbuf = (float2*)(sm + SM_ZOFF);
    int*    sact = (int*)(sm + SM_ZOFF + 2 * SM_ZF2);

    const int tid  = threadIdx.x;
    const int bid  = blockIdx.x;
    const int w    = tid >> 5;
    const int lane = tid & 31;
    const int bt   = lane >> 2;   // 0..7
    const int ct   = lane & 3;    // 0..3
    const int j0   = bid * 8;

    // load this block's U slice (contiguous) into padded smem
    {
        const float* src = g_Upk + (size_t)bid * 32 * RNN;
        #pragma unroll
        for (int r = 0; r < 32; r++) {
            int i4 = tid + 256 * r;          // 0..8191 float4s
            int c  = i4 >> 8;
            int k4 = (i4 & 255) << 2;
            *reinterpret_cast<float4*>(UsT + c * 1028 + k4) =
                *reinterpret_cast<const float4*>(src + c * RNN + k4);
        }
    }
    if (tid < NT) sact[tid] = g_active[tid];

    // per-thread bias for its 2 cells (e = tid, tid+256 -> b=e>>3, jj=e&7)
    float bsv[2][4];
    #pragma unroll
    for (int r = 0; r < 2; r++) {
        int jj = (tid + 256 * r) & 7;
        bsv[r][0] = bias[0 * RNN + j0 + jj];
        bsv[r][1] = bias[1 * RNN + j0 + jj];
        bsv[r][2] = bias[2 * RNN + j0 + jj];
        bsv[r][3] = bias[3 * RNN + j0 + jj];
    }
    __syncthreads();

    unsigned epoch = 0;
    int rb = 0;

    for (int t = 0; t < NT; t++) {
        if (!sact[t]) continue;
        const float* hread  = g_h2[rb];
        float*       hwrite = g_h2[rb ^ 1];

        float2 acc[8][8];
        #pragma unroll
        for (int i = 0; i < 8; i++)
            #pragma unroll
            for (int j = 0; j < 8; j++) acc[i][j] = make_float2(0.f, 0.f);

        // prefetch chunk 0
        #pragma unroll
        for (int r = 0; r < 8; r++) {
            int idx  = tid + 256 * r;
            int row  = idx >> 5;
            int col4 = (idx & 31) << 2;
            cp_async16(hb0 + row * 132 + col4, hread + row * RNN + col4);
        }
        CP_COMMIT();

        #pragma unroll 1
        for (int kc = 0; kc < 8; kc++) {
            CP_WAIT0();
            __syncthreads();
            if (kc < 7) {
                float* nb = (kc & 1) ? hb0 : hb1;
                const int k0n = (kc + 1) * 128;
                #pragma unroll
                for (int r = 0; r < 8; r++) {
                    int idx  = tid + 256 * r;
                    int row  = idx >> 5;
                    int col4 = (idx & 31) << 2;
                    cp_async16(nb + row * 132 + col4, hread + row * RNN + k0n + col4);
                }
                CP_COMMIT();
            }
            const float* hb = (kc & 1) ? hb1 : hb0;
            const int klocal = w * 16;
            const int kg = kc * 128 + klocal;
            #pragma unroll
            for (int kk = 0; kk < 16; kk += 2) {
                float2 h2[8], u2[8];
                #pragma unroll
                for (int i = 0; i < 8; i++)
                    h2[i] = *reinterpret_cast<const float2*>(hb + (bt + 8 * i) * 132 + klocal + kk);
                #pragma unroll
                for (int j = 0; j < 8; j++)
                    u2[j] = *reinterpret_cast<const float2*>(UsT + (ct + 4 * j) * 1028 + kg + kk);
                #pragma unroll
                for (int i = 0; i < 8; i++)
                    #pragma unroll
                    for (int j = 0; j < 8; j++)
                        acc[i][j] = ffma2(h2[i], u2[j], acc[i][j]);
            }
        }

        // reduce 8 warp-partials into zbuf
        #pragma unroll 1
        for (int ww = 0; ww < 8; ww++) {
            if (w == ww) {
                #pragma unroll
                for (int i = 0; i < 8; i++)
                    #pragma unroll
                    for (int j = 0; j < 8; j++) {
                        const int b = bt + 8 * i;
                        const int c = ct + 4 * j;
                        if (ww == 0) zbuf[b * 33 + c] = acc[i][j];
                        else {
                            float2 z = zbuf[b * 33 + c];
                            z.x += acc[i][j].x; z.y += acc[i][j].y;
                            zbuf[b * 33 + c] = z;
                        }
                    }
            }
            __syncthreads();
        }

        // fused cell update for owned 8 units x 64 batches
        #pragma unroll
        for (int r = 0; r < 2; r++) {
            const int e  = tid + 256 * r;
            const int b  = e >> 3;
            const int jj = e & 7;
            const float2 v0 = zbuf[b * 33 + jj];
            const float2 v1 = zbuf[b * 33 + 8 + jj];
            const float2 v2 = zbuf[b * 33 + 16 + jj];
            const float2 v3 = zbuf[b * 33 + 24 + jj];
            const float* xw = g_XW + ((size_t)t * NB + b) * Z4 + j0 + jj;
            const float zi = v0.x + v0.y + bsv[r][0] + xw[0];
            const float zf = v1.x + v1.y + bsv[r][1] + xw[RNN];
            const float zg = v2.x + v2.y + bsv[r][2] + xw[2 * RNN];
            const float zo = v3.x + v3.y + bsv[r][3] + xw[3 * RNN];
            const float si = 1.f / (1.f + expf(-zi));
            const float sf = 1.f / (1.f + expf(-zf));
            const float so = 1.f / (1.f + expf(-zo));
            const int   gi = b * RNN + j0 + jj;
            const float cn = sf * g_c[gi] + si * tanhf(zg);
            const float hn = so * tanhf(cn);
            const int   xv = x[b * NT + t];
            hwrite[gi] = (xv != 0) ? hn : hread[gi];
            if (xv != 0) g_c[gi] = cn;
            if (xv == 2) g_pooled[gi] += hn;
        }

        epoch++;
        gsync(epoch);
        rb ^= 1;
    }
}

// ---------------- head (unchanged) -----------------------------------------
__global__ __launch_bounds__(128) void head_kernel(const float* __restrict__ W1,
                                                   const float* __restrict__ b1,
                                                   const float* __restrict__ W2,
                                                   const float* __restrict__ b2,
                                                   const float* __restrict__ Wc,
                                                   const float* __restrict__ bc,
                                                   float* __restrict__ out) {
    const int b = blockIdx.x;
    const int tid = threadIdx.x;
    __shared__ float sp[RNN];
    __shared__ float h1s[HIDN];
    __shared__ float h2s[HIDN];
    __shared__ float lg[NLAB];

    for (int k = tid; k < RNN; k += 128) sp[k] = g_pooled[(size_t)b * RNN + k];
    __syncthreads();

    float a = b1[tid];
    for (int k = 0; k < RNN; k++) a += sp[k] * W1[(size_t)k * HIDN + tid];
    h1s[tid] = fmaxf(a, 0.f);
    __syncthreads();

    float a2 = b2[tid];
    for (int k = 0; k < HIDN; k++) a2 += h1s[k] * W2[(size_t)k * HIDN + tid];
    h2s[tid] = fmaxf(a2, 0.f);
    __syncthreads();

    if (tid < NLAB) {
        float l = bc[tid];
        for (int k = 0; k < HIDN; k++) l += h2s[k] * Wc[(size_t)k * NLAB + tid];
        lg[tid] = l;
    }
    __syncthreads();
    if (tid == 0) {
        const float mx = fmaxf(fmaxf(lg[0], lg[1]), fmaxf(lg[2], lg[3]));
        const float e0 = expf(lg[0] - mx), e1 = expf(lg[1] - mx);
        const float e2 = expf(lg[2] - mx), e3 = expf(lg[3] - mx);
        const float s = e0 + e1 + e2 + e3;
        out[b * 4 + 0] = e0 / s; out[b * 4 + 1] = e1 / s;
        out[b * 4 + 2] = e2 / s; out[b * 4 + 3] = e3 / s;
    }
}

// ---------------- launcher -------------------------------------------------
extern "C" void kernel_launch(void* const* d_in, const int* in_sizes, int n_in,
                              void* d_out, int out_size) {
    const int*   x    = (const int*)d_in[0];
    const float* emb  = (const float*)d_in[1];
    const float* W    = (const float*)d_in[2];
    const float* U    = (const float*)d_in[3];
    const float* bias = (const float*)d_in[4];
    const float* W1   = (const float*)d_in[5];
    const float* b1   = (const float*)d_in[6];
    const float* W2   = (const float*)d_in[7];
    const float* b2   = (const float*)d_in[8];
    const float* Wc   = (const float*)d_in[9];
    const float* bc   = (const float*)d_in[10];
    float* out = (float*)d_out;

    cudaFuncSetAttribute(rnn_kernel, cudaFuncAttributeMaxDynamicSharedMemorySize, SMEM_RNN);

    prep_kernel<<<1, 256>>>(x);
    zero_kernel<<<256, 256>>>();
    upack_kernel<<<(RNN * Z4) / 256, 256>>>(U);
    xw_kernel<<<dim3(Z4 / BN, NT), 128>>>(x, emb, W);
    rnn_kernel<<<GRID_R, 256, SMEM_RNN>>>(x, bias);
    head_kernel<<<NB, 128>>>(W1, b1, W2, b2, Wc, bc, out);
}

// round 4
// speedup vs baseline: 1.9434x; 1.9434x over previous
#include <cuda_runtime.h>
#include <cuda_bf16.h>
#include <math.h>
#include <stdint.h>

#define NB   64
#define NT   256
#define EMBD 512
#define RNN  1024
#define Z4   4096
#define HIDN 128
#define NLAB 4

#define BM 64
#define BN 128
#define BK 16

// ---------------- static device scratch ----------------------------------
__device__ float g_XW[(size_t)NT * NB * Z4];            // emb[x] @ W
__device__ __nv_bfloat16 g_UThi[(size_t)Z4 * RNN];      // U^T hi, [n][k]
__device__ __nv_bfloat16 g_UTlo[(size_t)Z4 * RNN];      // U^T lo, [n][k]
__device__ __nv_bfloat16 g_Hs[128 * RNN];               // [h_hi(64 rows); h_lo(64 rows)]
__device__ float g_zp[4][NB * Z4];                      // partials: [s*2+ks][b][n]
__device__ float g_c[NB * RNN];
__device__ float g_pooled[NB * RNN];
__device__ int   g_active[NT];

// ---------------- helpers --------------------------------------------------
__device__ __forceinline__ uint32_t smem_u32(const void* p) {
    return (uint32_t)__cvta_generic_to_shared(p);
}
__device__ __forceinline__ void cp_async16(uint32_t smem_dst, const void* gsrc) {
    asm volatile("cp.async.cg.shared.global [%0], [%1], 16;" :: "r"(smem_dst), "l"(gsrc));
}
#define CP_COMMIT() asm volatile("cp.async.commit_group;" ::: "memory")

__device__ __forceinline__ void ldsm_x4(uint32_t& r0, uint32_t& r1,
                                        uint32_t& r2, uint32_t& r3, uint32_t addr) {
    asm volatile("ldmatrix.sync.aligned.m8n8.x4.shared.b16 {%0,%1,%2,%3}, [%4];"
                 : "=r"(r0), "=r"(r1), "=r"(r2), "=r"(r3) : "r"(addr));
}
__device__ __forceinline__ void mma_bf16(float* c, uint32_t a0, uint32_t a1,
                                         uint32_t a2, uint32_t a3,
                                         uint32_t b0, uint32_t b1) {
    asm volatile("mma.sync.aligned.m16n8k16.row.col.f32.bf16.bf16.f32 "
                 "{%0,%1,%2,%3}, {%4,%5,%6,%7}, {%8,%9}, {%0,%1,%2,%3};"
                 : "+f"(c[0]), "+f"(c[1]), "+f"(c[2]), "+f"(c[3])
                 : "r"(a0), "r"(a1), "r"(a2), "r"(a3), "r"(b0), "r"(b1));
}
__device__ __forceinline__ float2 ffma2(float2 a, float2 b, float2 c) {
    unsigned long long ra = reinterpret_cast<unsigned long long&>(a);
    unsigned long long rb = reinterpret_cast<unsigned long long&>(b);
    unsigned long long rc = reinterpret_cast<unsigned long long&>(c);
    unsigned long long rd;
    asm("fma.rn.f32x2 %0, %1, %2, %3;" : "=l"(rd) : "l"(ra), "l"(rb), "l"(rc));
    return reinterpret_cast<float2&>(rd);
}

// ---------------- prep -----------------------------------------------------
__global__ void prep_kernel(const int* __restrict__ x) {
    int t = threadIdx.x;
    if (t < NT) {
        int act = 0;
        for (int b = 0; b < NB; b++) act |= (x[b * NT + t] != 0);
        g_active[t] = act;
    }
}

__global__ void zero_kernel() {
    int i = blockIdx.x * blockDim.x + threadIdx.x;   // 65536
    if (i < NB * RNN) {
        g_c[i] = 0.f; g_pooled[i] = 0.f;
        ((uint32_t*)g_Hs)[i] = 0u;                   // 65536 u32 = 128x1024 bf16
    }
}

// ---------------- tiled transpose + split: U -> UThi/UTlo ------------------
__global__ __launch_bounds__(256) void upack_kernel(const float* __restrict__ U) {
    __shared__ float tile[64][65];
    const int k0 = blockIdx.x * 64;
    const int n0 = blockIdx.y * 64;
    const int tid = threadIdx.x;
    #pragma unroll
    for (int it = 0; it < 16; it++) {
        int r = it * 4 + (tid >> 6);
        int c = tid & 63;
        tile[r][c] = U[(size_t)(k0 + r) * Z4 + n0 + c];
    }
    __syncthreads();
    #pragma unroll
    for (int it = 0; it < 16; it++) {
        int n = it * 4 + (tid >> 6);
        int k = tid & 63;
        float v = tile[k][n];
        __nv_bfloat16 hi = __float2bfloat16(v);
        g_UThi[(size_t)(n0 + n) * RNN + k0 + k] = hi;
        g_UTlo[(size_t)(n0 + n) * RNN + k0 + k] =
            __float2bfloat16(v - __bfloat162float(hi));
    }
}

// ---------------- XW = emb[x] @ W (fp32x2 SIMT, known-good from R1) --------
__global__ __launch_bounds__(128) void xw_kernel(const int* __restrict__ x,
                                                 const float* __restrict__ emb,
                                                 const float* __restrict__ W) {
    const int t = blockIdx.y;
    if (!g_active[t]) return;
    const int n0 = blockIdx.x * BN;

    __shared__ float As[2][BK][BM];
    __shared__ float Bs[2][BK][BN];
    __shared__ int idxs[NB];

    const int tid = threadIdx.x;
    if (tid < NB) idxs[tid] = x[tid * NT + t];
    __syncthreads();

    const int am   = tid >> 2;
    const int ak   = (tid & 3) << 2;
    const int brow = tid >> 5;
    const int bcol = (tid & 31) << 2;
    const int tb = tid >> 4;
    const int tc = tid & 15;
    const int m0 = tb * 8;
    const int c0 = tc * 8;

    const size_t eA0 = (size_t)idxs[am] * EMBD;
    const size_t eA1 = (size_t)idxs[am + 32] * EMBD;

    float2 acc[8][4];
    #pragma unroll
    for (int i = 0; i < 8; i++)
        #pragma unroll
        for (int j = 0; j < 4; j++) acc[i][j] = make_float2(0.f, 0.f);

    float4 ra0, ra1, rb[4];

    ra0 = *reinterpret_cast<const float4*>(emb + eA0 + ak);
    ra1 = *reinterpret_cast<const float4*>(emb + eA1 + ak);
    #pragma unroll
    for (int j = 0; j < 4; j++)
        rb[j] = *reinterpret_cast<const float4*>(W + (size_t)(brow + 4 * j) * Z4 + n0 + bcol);
    As[0][ak + 0][am] = ra0.x; As[0][ak + 1][am] = ra0.y;
    As[0][ak + 2][am] = ra0.z; As[0][ak + 3][am] = ra0.w;
    As[0][ak + 0][am + 32] = ra1.x; As[0][ak + 1][am + 32] = ra1.y;
    As[0][ak + 2][am + 32] = ra1.z; As[0][ak + 3][am + 32] = ra1.w;
    #pragma unroll
    for (int j = 0; j < 4; j++)
        *reinterpret_cast<float4*>(&Bs[0][brow + 4 * j][bcol]) = rb[j];
    __syncthreads();

    const int nch = EMBD / BK;
    for (int ch = 0; ch < nch; ch++) {
        const int buf = ch & 1;
        if (ch + 1 < nch) {
            const int k0 = (ch + 1) * BK;
            ra0 = *reinterpret_cast<const float4*>(emb + eA0 + k0 + ak);
            ra1 = *reinterpret_cast<const float4*>(emb + eA1 + k0 + ak);
            #pragma unroll
            for (int j = 0; j < 4; j++)
                rb[j] = *reinterpret_cast<const float4*>(W + (size_t)(k0 + brow + 4 * j) * Z4 + n0 + bcol);
        }
        #pragma unroll
        for (int kk = 0; kk < BK; kk++) {
            const float4 a0 = *reinterpret_cast<const float4*>(&As[buf][kk][m0]);
            const float4 a1 = *reinterpret_cast<const float4*>(&As[buf][kk][m0 + 4]);
            const float4 b0 = *reinterpret_cast<const float4*>(&Bs[buf][kk][c0]);
            const float4 b1 = *reinterpret_cast<const float4*>(&Bs[buf][kk][c0 + 4]);
            float2 bv[4];
            bv[0] = make_float2(b0.x, b0.y); bv[1] = make_float2(b0.z, b0.w);
            bv[2] = make_float2(b1.x, b1.y); bv[3] = make_float2(b1.z, b1.w);
            const float av[8] = {a0.x, a0.y, a0.z, a0.w, a1.x, a1.y, a1.z, a1.w};
            #pragma unroll
            for (int i = 0; i < 8; i++) {
                const float2 as = make_float2(av[i], av[i]);
                #pragma unroll
                for (int j = 0; j < 4; j++) acc[i][j] = ffma2(as, bv[j], acc[i][j]);
            }
        }
        if (ch + 1 < nch) {
            const int nb = (ch + 1) & 1;
            As[nb][ak + 0][am] = ra0.x; As[nb][ak + 1][am] = ra0.y;
            As[nb][ak + 2][am] = ra0.z; As[nb][ak + 3][am] = ra0.w;
            As[nb][ak + 0][am + 32] = ra1.x; As[nb][ak + 1][am + 32] = ra1.y;
            As[nb][ak + 2][am + 32] = ra1.z; As[nb][ak + 3][am + 32] = ra1.w;
            #pragma unroll
            for (int j = 0; j < 4; j++)
                *reinterpret_cast<float4*>(&Bs[nb][brow + 4 * j][bcol]) = rb[j];
        }
        __syncthreads();
    }

    float* C = g_XW + (size_t)t * NB * Z4;
    #pragma unroll
    for (int i = 0; i < 8; i++) {
        const int row = m0 + i;
        float4 v0 = make_float4(acc[i][0].x, acc[i][0].y, acc[i][1].x, acc[i][1].y);
        float4 v1 = make_float4(acc[i][2].x, acc[i][2].y, acc[i][3].x, acc[i][3].y);
        *reinterpret_cast<float4*>(C + (size_t)row * Z4 + n0 + c0) = v0;
        *reinterpret_cast<float4*>(C + (size_t)row * Z4 + n0 + c0 + 4) = v1;
    }
}

// ---------------- per-step HMMA GEMM: zp[s*2+ks] = fold(Hs @ UT_s^T) -------
// grid (32 n-tiles, 2 s, 2 ks) x 256 threads (8 warps).
// Block: M=128 (hi/lo stacked), N=128, K=512 (ks slice), chunks of K=64,
// double-buffered cp.async, warp owns n16 x m128.
#define ZCHUNKS 8
#define ZBUF_BYTES 32768                     // A 16KB + B 16KB per buffer
#define GZ_SMEM (1024 + 2 * ZBUF_BYTES)

__global__ __launch_bounds__(256) void zgemm_kernel(int t) {
    if (!g_active[t]) return;

    extern __shared__ char dyn[];
    const uint32_t tb = (smem_u32(dyn) + 1023u) & ~1023u;

    const int tid  = threadIdx.x;
    const int w    = tid >> 5;
    const int lane = tid & 31;
    const int n0   = blockIdx.x * 128;
    const int s    = blockIdx.y;
    const int ks   = blockIdx.z;
    const int kbase = ks * 512;

    const __nv_bfloat16* Bsrc = (s ? g_UTlo : g_UThi) + (size_t)n0 * RNN;

    // c[mtile 0..7][ntile 0..1][4]
    float c[8][2][4];
    #pragma unroll
    for (int i = 0; i < 8; i++)
        #pragma unroll
        for (int j = 0; j < 2; j++)
            #pragma unroll
            for (int r = 0; r < 4; r++) c[i][j][r] = 0.f;

    auto load_chunk = [&](int ch, int slot) {
        const uint32_t ab = tb + slot * ZBUF_BYTES;
        const uint32_t bb = ab + 16384;
        const int kg = kbase + ch * 64;
        #pragma unroll
        for (int r = 0; r < 4; r++) {
            const int o   = tid + 256 * r;   // 0..1023
            const int row = o >> 3;
            const int cb  = o & 7;
            uint32_t off = (uint32_t)(row * 128 + cb * 16);
            uint32_t sw  = off ^ ((off >> 3) & 0x70);
            cp_async16(ab + sw, g_Hs + (size_t)row * RNN + kg + cb * 8);
            cp_async16(bb + sw, Bsrc + (size_t)row * RNN + kg + cb * 8);
        }
        CP_COMMIT();
    };

    load_chunk(0, 0);

    const int wn0 = w * 16;
    // per-lane ldmatrix row/col components (shared by A and B tiles)
    const int lrow = ((lane >> 3) & 1) * 8 + (lane & 7);  // row within 16
    const int lcolb = (lane >> 4) * 16;                   // 0 or 16 bytes (k+8)

    for (int ch = 0; ch < ZCHUNKS; ch++) {
        if (ch + 1 < ZCHUNKS) load_chunk(ch + 1, (ch + 1) & 1);
        if (ch + 1 < ZCHUNKS) asm volatile("cp.async.wait_group 1;" ::: "memory");
        else                  asm volatile("cp.async.wait_group 0;" ::: "memory");
        __syncthreads();

        const uint32_t ab = tb + (ch & 1) * ZBUF_BYTES;
        const uint32_t bb = ab + 16384;

        #pragma unroll
        for (int kk = 0; kk < 4; kk++) {
            // B tile: n16 x k16 at (wn0, kk*16)
            uint32_t boff = (uint32_t)((wn0 + lrow) * 128 + kk * 32 + lcolb);
            uint32_t baddr = bb + (boff ^ ((boff >> 3) & 0x70));
            uint32_t b0, b1, b2, b3;
            ldsm_x4(b0, b1, b2, b3, baddr);
            // ntile0 frags {b0,b2}, ntile1 {b1,b3}
            #pragma unroll
            for (int mt = 0; mt < 8; mt++) {
                uint32_t aoff = (uint32_t)((mt * 16 + lrow) * 128 + kk * 32 + lcolb);
                uint32_t aaddr = ab + (aoff ^ ((aoff >> 3) & 0x70));
                uint32_t a0, a1, a2, a3;
                ldsm_x4(a0, a1, a2, a3, aaddr);
                mma_bf16(c[mt][0], a0, a1, a2, a3, b0, b2);
                mma_bf16(c[mt][1], a0, a1, a2, a3, b1, b3);
            }
        }
        __syncthreads();
    }

    // epilogue: fold hi rows (mt) + lo rows (mt+4), write fp32 partials
    float* zb = g_zp[s * 2 + ks];
    #pragma unroll
    for (int mt = 0; mt < 4; mt++) {
        #pragma unroll
        for (int nt = 0; nt < 2; nt++) {
            const int row = mt * 16 + (lane >> 2);
            const int col = n0 + wn0 + nt * 8 + (lane & 3) * 2;
            float2 v01 = make_float2(c[mt][nt][0] + c[mt + 4][nt][0],
                                     c[mt][nt][1] + c[mt + 4][nt][1]);
            float2 v23 = make_float2(c[mt][nt][2] + c[mt + 4][nt][2],
                                     c[mt][nt][3] + c[mt + 4][nt][3]);
            *reinterpret_cast<float2*>(zb + (size_t)row * Z4 + col) = v01;
            *reinterpret_cast<float2*>(zb + (size_t)(row + 8) * Z4 + col) = v23;
        }
    }
}

// ---------------- LSTM cell update (folds 4 partials, writes bf16 split) ---
__global__ void cell_kernel(const int* __restrict__ x, const float* __restrict__ bias, int t) {
    if (!g_active[t]) return;
    const int idx = blockIdx.x * blockDim.x + threadIdx.x;  // 0..65535
    const int b = idx >> 10;
    const int hid = idx & 1023;

    const float* xw = g_XW + ((size_t)t * NB + b) * Z4;
    float z[4];
    #pragma unroll
    for (int g = 0; g < 4; g++) {
        const int n = g * RNN + hid;
        z[g] = bias[n] + xw[n]
             + g_zp[0][(size_t)b * Z4 + n] + g_zp[1][(size_t)b * Z4 + n]
             + g_zp[2][(size_t)b * Z4 + n] + g_zp[3][(size_t)b * Z4 + n];
    }
    const float si = 1.f / (1.f + expf(-z[0]));
    const float sf = 1.f / (1.f + expf(-z[1]));
    const float tg = tanhf(z[2]);
    const float so = 1.f / (1.f + expf(-z[3]));
    const int gi = b * RNN + hid;
    const float cn = sf * g_c[gi] + si * tg;
    const float hn = so * tanhf(cn);
    const int xv = x[b * NT + t];
    if (xv != 0) {
        g_c[gi] = cn;
        __nv_bfloat16 hi = __float2bfloat16(hn);
        g_Hs[b * RNN + hid] = hi;
        g_Hs[(b + 64) * RNN + hid] = __float2bfloat16(hn - __bfloat162float(hi));
    }
    if (xv == 2) g_pooled[gi] += hn;
}

// ---------------- head -----------------------------------------------------
__global__ __launch_bounds__(128) void head_kernel(const float* __restrict__ W1,
                                                   const float* __restrict__ b1,
                                                   const float* __restrict__ W2,
                                                   const float* __restrict__ b2,
                                                   const float* __restrict__ Wc,
                                                   const float* __restrict__ bc,
                                                   float* __restrict__ out) {
    const int b = blockIdx.x;
    const int tid = threadIdx.x;
    __shared__ float sp[RNN];
    __shared__ float h1s[HIDN];
    __shared__ float h2s[HIDN];
    __shared__ float lg[NLAB];

    for (int k = tid; k < RNN; k += 128) sp[k] = g_pooled[(size_t)b * RNN + k];
    __syncthreads();

    float a = b1[tid];
    for (int k = 0; k < RNN; k++) a += sp[k] * W1[(size_t)k * HIDN + tid];
    h1s[tid] = fmaxf(a, 0.f);
    __syncthreads();

    float a2 = b2[tid];
    for (int k = 0; k < HIDN; k++) a2 += h1s[k] * W2[(size_t)k * HIDN + tid];
    h2s[tid] = fmaxf(a2, 0.f);
    __syncthreads();

    if (tid < NLAB) {
        float l = bc[tid];
        for (int k = 0; k < HIDN; k++) l += h2s[k] * Wc[(size_t)k * NLAB + tid];
        lg[tid] = l;
    }
    __syncthreads();
    if (tid == 0) {
        const float mx = fmaxf(fmaxf(lg[0], lg[1]), fmaxf(lg[2], lg[3]));
        const float e0 = expf(lg[0] - mx), e1 = expf(lg[1] - mx);
        const float e2 = expf(lg[2] - mx), e3 = expf(lg[3] - mx);
        const float sden = e0 + e1 + e2 + e3;
        out[b * 4 + 0] = e0 / sden; out[b * 4 + 1] = e1 / sden;
        out[b * 4 + 2] = e2 / sden; out[b * 4 + 3] = e3 / sden;
    }
}

// ---------------- launcher -------------------------------------------------
extern "C" void kernel_launch(void* const* d_in, const int* in_sizes, int n_in,
                              void* d_out, int out_size) {
    const int*   x    = (const int*)d_in[0];
    const float* emb  = (const float*)d_in[1];
    const float* W    = (const float*)d_in[2];
    const float* U    = (const float*)d_in[3];
    const float* bias = (const float*)d_in[4];
    const float* W1   = (const float*)d_in[5];
    const float* b1   = (const float*)d_in[6];
    const float* W2   = (const float*)d_in[7];
    const float* b2   = (const float*)d_in[8];
    const float* Wc   = (const float*)d_in[9];
    const float* bc   = (const float*)d_in[10];
    float* out = (float*)d_out;

    cudaFuncSetAttribute(zgemm_kernel, cudaFuncAttributeMaxDynamicSharedMemorySize, GZ_SMEM);

    prep_kernel<<<1, 256>>>(x);
    zero_kernel<<<256, 256>>>();
    upack_kernel<<<dim3(RNN / 64, Z4 / 64), 256>>>(U);
    xw_kernel<<<dim3(Z4 / BN, NT), 128>>>(x, emb, W);
    for (int t = 0; t < NT; t++) {
        zgemm_kernel<<<dim3(32, 2, 2), 256, GZ_SMEM>>>(t);
        cell_kernel<<<256, 256>>>(x, bias, t);
    }
    head_kernel<<<NB, 128>>>(W1, b1, W2, b2, Wc, bc, out);
}

// round 5
// speedup vs baseline: 2.1280x; 1.0950x over previous
#include <cuda_runtime.h>
#include <cuda_bf16.h>
#include <math.h>
#include <stdint.h>

#define NB   64
#define NT   256
#define EMBD 512
#define VOCAB 32000
#define RNN  1024
#define Z4   4096
#define HIDN 128
#define NLAB 4

// ---------------- static device scratch ----------------------------------
__device__ float g_XW[(size_t)NT * NB * Z4];            // emb[x] @ W
__device__ __nv_bfloat16 g_UThi[(size_t)Z4 * RNN];      // U^T hi, [n][k]
__device__ __nv_bfloat16 g_UTlo[(size_t)Z4 * RNN];      // U^T lo, [n][k]
__device__ __nv_bfloat16 g_WThi[(size_t)Z4 * EMBD];     // W^T hi, [n][k]
__device__ __nv_bfloat16 g_WTlo[(size_t)Z4 * EMBD];     // W^T lo, [n][k]
__device__ __nv_bfloat16 g_Ehi[(size_t)VOCAB * EMBD];   // emb hi
__device__ __nv_bfloat16 g_Elo[(size_t)VOCAB * EMBD];   // emb lo
__device__ __nv_bfloat16 g_Hs[128 * RNN];               // [h_hi(64); h_lo(64)]
__device__ float g_zp[4][NB * Z4];                      // z partials
__device__ float g_c[NB * RNN];
__device__ float g_pooled[NB * RNN];
__device__ int   g_active[NT];

// ---------------- helpers --------------------------------------------------
__device__ __forceinline__ uint32_t smem_u32(const void* p) {
    return (uint32_t)__cvta_generic_to_shared(p);
}
__device__ __forceinline__ void cp_async16(uint32_t smem_dst, const void* gsrc) {
    asm volatile("cp.async.cg.shared.global [%0], [%1], 16;" :: "r"(smem_dst), "l"(gsrc));
}
#define CP_COMMIT() asm volatile("cp.async.commit_group;" ::: "memory")

__device__ __forceinline__ void ldsm_x4(uint32_t& r0, uint32_t& r1,
                                        uint32_t& r2, uint32_t& r3, uint32_t addr) {
    asm volatile("ldmatrix.sync.aligned.m8n8.x4.shared.b16 {%0,%1,%2,%3}, [%4];"
                 : "=r"(r0), "=r"(r1), "=r"(r2), "=r"(r3) : "r"(addr));
}
__device__ __forceinline__ void mma_bf16(float* c, uint32_t a0, uint32_t a1,
                                         uint32_t a2, uint32_t a3,
                                         uint32_t b0, uint32_t b1) {
    asm volatile("mma.sync.aligned.m16n8k16.row.col.f32.bf16.bf16.f32 "
                 "{%0,%1,%2,%3}, {%4,%5,%6,%7}, {%8,%9}, {%0,%1,%2,%3};"
                 : "+f"(c[0]), "+f"(c[1]), "+f"(c[2]), "+f"(c[3])
                 : "r"(a0), "r"(a1), "r"(a2), "r"(a3), "r"(b0), "r"(b1));
}

// ---------------- prep -----------------------------------------------------
__global__ void prep_kernel(const int* __restrict__ x) {
    int t = threadIdx.x;
    if (t < NT) {
        int act = 0;
        for (int b = 0; b < NB; b++) act |= (x[b * NT + t] != 0);
        g_active[t] = act;
    }
}

__global__ void zero_kernel() {
    int i = blockIdx.x * blockDim.x + threadIdx.x;   // 65536
    if (i < NB * RNN) {
        g_c[i] = 0.f; g_pooled[i] = 0.f;
        ((uint32_t*)g_Hs)[i] = 0u;
    }
}

// ---------------- emb split ------------------------------------------------
__global__ __launch_bounds__(256) void esplit_kernel(const float* __restrict__ emb) {
    size_t i = (size_t)blockIdx.x * 256 + threadIdx.x;   // VOCAB*EMBD = 16.384M
    float v = emb[i];
    __nv_bfloat16 hi = __float2bfloat16(v);
    g_Ehi[i] = hi;
    g_Elo[i] = __float2bfloat16(v - __bfloat162float(hi));
}

// ---------------- transpose+split: U and W ---------------------------------
__global__ __launch_bounds__(256) void upack_kernel(const float* __restrict__ U) {
    __shared__ float tile[64][65];
    const int k0 = blockIdx.x * 64;
    const int n0 = blockIdx.y * 64;
    const int tid = threadIdx.x;
    #pragma unroll
    for (int it = 0; it < 16; it++) {
        int r = it * 4 + (tid >> 6);
        int c = tid & 63;
        tile[r][c] = U[(size_t)(k0 + r) * Z4 + n0 + c];
    }
    __syncthreads();
    #pragma unroll
    for (int it = 0; it < 16; it++) {
        int n = it * 4 + (tid >> 6);
        int k = tid & 63;
        float v = tile[k][n];
        __nv_bfloat16 hi = __float2bfloat16(v);
        g_UThi[(size_t)(n0 + n) * RNN + k0 + k] = hi;
        g_UTlo[(size_t)(n0 + n) * RNN + k0 + k] =
            __float2bfloat16(v - __bfloat162float(hi));
    }
}

__global__ __launch_bounds__(256) void wpack_kernel(const float* __restrict__ W) {
    __shared__ float tile[64][65];
    const int k0 = blockIdx.x * 64;    // 8 blocks (EMBD=512)
    const int n0 = blockIdx.y * 64;    // 64 blocks
    const int tid = threadIdx.x;
    #pragma unroll
    for (int it = 0; it < 16; it++) {
        int r = it * 4 + (tid >> 6);
        int c = tid & 63;
        tile[r][c] = W[(size_t)(k0 + r) * Z4 + n0 + c];
    }
    __syncthreads();
    #pragma unroll
    for (int it = 0; it < 16; it++) {
        int n = it * 4 + (tid >> 6);
        int k = tid & 63;
        float v = tile[k][n];
        __nv_bfloat16 hi = __float2bfloat16(v);
        g_WThi[(size_t)(n0 + n) * EMBD + k0 + k] = hi;
        g_WTlo[(size_t)(n0 + n) * EMBD + k0 + k] =
            __float2bfloat16(v - __bfloat162float(hi));
    }
}

// ---------------- HMMA input projection: XW[t] = emb[x_t] @ W --------------
// grid (32 n-tiles, NT) x 256 threads. M=128=[e_hi;e_lo], N=128,
// K = 512 x 2 passes (W_hi then W_lo) accumulated in registers; epilogue
// folds rows m and m+64 -> exact product.
#define XCHUNKS 16
#define BUF_BYTES 32768
#define GEMM_SMEM (1024 + 2 * BUF_BYTES)

__global__ __launch_bounds__(256) void xw_mma_kernel(const int* __restrict__ x) {
    const int t = blockIdx.y;
    if (!g_active[t]) return;

    extern __shared__ char dyn[];
    __shared__ int idxs[64];
    const uint32_t tb = (smem_u32(dyn) + 1023u) & ~1023u;

    const int tid  = threadIdx.x;
    const int w    = tid >> 5;
    const int lane = tid & 31;
    const int n0   = blockIdx.x * 128;

    if (tid < 64) idxs[tid] = x[tid * NT + t];
    __syncthreads();

    float c[8][2][4];
    #pragma unroll
    for (int i = 0; i < 8; i++)
        #pragma unroll
        for (int j = 0; j < 2; j++)
            #pragma unroll
            for (int r = 0; r < 4; r++) c[i][j][r] = 0.f;

    auto load_chunk = [&](int ch, int slot) {
        const uint32_t ab = tb + slot * BUF_BYTES;
        const uint32_t bb = ab + 16384;
        const int pass = ch >> 3;
        const int kg = (ch & 7) * 64;
        const __nv_bfloat16* Bsrc =
            (pass ? g_WTlo : g_WThi) + (size_t)n0 * EMBD + kg;
        #pragma unroll
        for (int r = 0; r < 4; r++) {
            const int o   = tid + 256 * r;   // 0..1023
            const int row = o >> 3;
            const int cb  = o & 7;
            uint32_t off = (uint32_t)(row * 128 + cb * 16);
            uint32_t sw  = off ^ ((off >> 3) & 0x70);
            const __nv_bfloat16* asrc =
                (row < 64) ? (g_Ehi + (size_t)idxs[row] * EMBD + kg + cb * 8)
                           : (g_Elo + (size_t)idxs[row - 64] * EMBD + kg + cb * 8);
            cp_async16(ab + sw, asrc);
            cp_async16(bb + sw, Bsrc + (size_t)row * EMBD + cb * 8);
        }
        CP_COMMIT();
    };

    load_chunk(0, 0);

    const int wn0 = w * 16;
    const int lrow = ((lane >> 3) & 1) * 8 + (lane & 7);
    const int lcolb = (lane >> 4) * 16;

    for (int ch = 0; ch < XCHUNKS; ch++) {
        if (ch + 1 < XCHUNKS) load_chunk(ch + 1, (ch + 1) & 1);
        if (ch + 1 < XCHUNKS) asm volatile("cp.async.wait_group 1;" ::: "memory");
        else                  asm volatile("cp.async.wait_group 0;" ::: "memory");
        __syncthreads();

        const uint32_t ab = tb + (ch & 1) * BUF_BYTES;
        const uint32_t bb = ab + 16384;

        #pragma unroll
        for (int kk = 0; kk < 4; kk++) {
            uint32_t boff = (uint32_t)((wn0 + lrow) * 128 + kk * 32 + lcolb);
            uint32_t baddr = bb + (boff ^ ((boff >> 3) & 0x70));
            uint32_t b0, b1, b2, b3;
            ldsm_x4(b0, b1, b2, b3, baddr);
            #pragma unroll
            for (int mt = 0; mt < 8; mt++) {
                uint32_t aoff = (uint32_t)((mt * 16 + lrow) * 128 + kk * 32 + lcolb);
                uint32_t aaddr = ab + (aoff ^ ((aoff >> 3) & 0x70));
                uint32_t a0, a1, a2, a3;
                ldsm_x4(a0, a1, a2, a3, aaddr);
                mma_bf16(c[mt][0], a0, a1, a2, a3, b0, b2);
                mma_bf16(c[mt][1], a0, a1, a2, a3, b1, b3);
            }
        }
        __syncthreads();
    }

    float* C = g_XW + (size_t)t * NB * Z4;
    #pragma unroll
    for (int mt = 0; mt < 4; mt++) {
        #pragma unroll
        for (int nt = 0; nt < 2; nt++) {
            const int row = mt * 16 + (lane >> 2);
            const int col = n0 + wn0 + nt * 8 + (lane & 3) * 2;
            float2 v01 = make_float2(c[mt][nt][0] + c[mt + 4][nt][0],
                                     c[mt][nt][1] + c[mt + 4][nt][1]);
            float2 v23 = make_float2(c[mt][nt][2] + c[mt + 4][nt][2],
                                     c[mt][nt][3] + c[mt + 4][nt][3]);
            *reinterpret_cast<float2*>(C + (size_t)row * Z4 + col) = v01;
            *reinterpret_cast<float2*>(C + (size_t)(row + 8) * Z4 + col) = v23;
        }
    }
}

// ---------------- per-step HMMA GEMM: zp[s*2+ks] = fold(Hs @ UT_s^T) -------
#define ZCHUNKS 8

__global__ __launch_bounds__(256) void zgemm_kernel(int t) {
    if (!g_active[t]) return;

    extern __shared__ char dyn[];
    const uint32_t tb = (smem_u32(dyn) + 1023u) & ~1023u;

    const int tid  = threadIdx.x;
    const int w    = tid >> 5;
    const int lane = tid & 31;
    const int n0   = blockIdx.x * 128;
    const int s    = blockIdx.y;
    const int ks   = blockIdx.z;
    const int kbase = ks * 512;

    const __nv_bfloat16* Bsrc = (s ? g_UTlo : g_UThi) + (size_t)n0 * RNN;

    float c[8][2][4];
    #pragma unroll
    for (int i = 0; i < 8; i++)
        #pragma unroll
        for (int j = 0; j < 2; j++)
            #pragma unroll
            for (int r = 0; r < 4; r++) c[i][j][r] = 0.f;

    auto load_chunk = [&](int ch, int slot) {
        const uint32_t ab = tb + slot * BUF_BYTES;
        const uint32_t bb = ab + 16384;
        const int kg = kbase + ch * 64;
        #pragma unroll
        for (int r = 0; r < 4; r++) {
            const int o   = tid + 256 * r;
            const int row = o >> 3;
            const int cb  = o & 7;
            uint32_t off = (uint32_t)(row * 128 + cb * 16);
            uint32_t sw  = off ^ ((off >> 3) & 0x70);
            cp_async16(ab + sw, g_Hs + (size_t)row * RNN + kg + cb * 8);
            cp_async16(bb + sw, Bsrc + (size_t)row * RNN + kg + cb * 8);
        }
        CP_COMMIT();
    };

    load_chunk(0, 0);

    const int wn0 = w * 16;
    const int lrow = ((lane >> 3) & 1) * 8 + (lane & 7);
    const int lcolb = (lane >> 4) * 16;

    for (int ch = 0; ch < ZCHUNKS; ch++) {
        if (ch + 1 < ZCHUNKS) load_chunk(ch + 1, (ch + 1) & 1);
        if (ch + 1 < ZCHUNKS) asm volatile("cp.async.wait_group 1;" ::: "memory");
        else                  asm volatile("cp.async.wait_group 0;" ::: "memory");
        __syncthreads();

        const uint32_t ab = tb + (ch & 1) * BUF_BYTES;
        const uint32_t bb = ab + 16384;

        #pragma unroll
        for (int kk = 0; kk < 4; kk++) {
            uint32_t boff = (uint32_t)((wn0 + lrow) * 128 + kk * 32 + lcolb);
            uint32_t baddr = bb + (boff ^ ((boff >> 3) & 0x70));
            uint32_t b0, b1, b2, b3;
            ldsm_x4(b0, b1, b2, b3, baddr);
            #pragma unroll
            for (int mt = 0; mt < 8; mt++) {
                uint32_t aoff = (uint32_t)((mt * 16 + lrow) * 128 + kk * 32 + lcolb);
                uint32_t aaddr = ab + (aoff ^ ((aoff >> 3) & 0x70));
                uint32_t a0, a1, a2, a3;
                ldsm_x4(a0, a1, a2, a3, aaddr);
                mma_bf16(c[mt][0], a0, a1, a2, a3, b0, b2);
                mma_bf16(c[mt][1], a0, a1, a2, a3, b1, b3);
            }
        }
        __syncthreads();
    }

    float* zb = g_zp[s * 2 + ks];
    #pragma unroll
    for (int mt = 0; mt < 4; mt++) {
        #pragma unroll
        for (int nt = 0; nt < 2; nt++) {
            const int row = mt * 16 + (lane >> 2);
            const int col = n0 + wn0 + nt * 8 + (lane & 3) * 2;
            float2 v01 = make_float2(c[mt][nt][0] + c[mt + 4][nt][0],
                                     c[mt][nt][1] + c[mt + 4][nt][1]);
            float2 v23 = make_float2(c[mt][nt][2] + c[mt + 4][nt][2],
                                     c[mt][nt][3] + c[mt + 4][nt][3]);
            *reinterpret_cast<float2*>(zb + (size_t)row * Z4 + col) = v01;
            *reinterpret_cast<float2*>(zb + (size_t)(row + 8) * Z4 + col) = v23;
        }
    }
}

// ---------------- LSTM cell update -----------------------------------------
__global__ void cell_kernel(const int* __restrict__ x, const float* __restrict__ bias, int t) {
    if (!g_active[t]) return;
    const int idx = blockIdx.x * blockDim.x + threadIdx.x;
    const int b = idx >> 10;
    const int hid = idx & 1023;

    const float* xw = g_XW + ((size_t)t * NB + b) * Z4;
    float z[4];
    #pragma unroll
    for (int g = 0; g < 4; g++) {
        const int n = g * RNN + hid;
        z[g] = bias[n] + xw[n]
             + g_zp[0][(size_t)b * Z4 + n] + g_zp[1][(size_t)b * Z4 + n]
             + g_zp[2][(size_t)b * Z4 + n] + g_zp[3][(size_t)b * Z4 + n];
    }
    const float si = 1.f / (1.f + expf(-z[0]));
    const float sf = 1.f / (1.f + expf(-z[1]));
    const float tg = tanhf(z[2]);
    const float so = 1.f / (1.f + expf(-z[3]));
    const int gi = b * RNN + hid;
    const float cn = sf * g_c[gi] + si * tg;
    const float hn = so * tanhf(cn);
    const int xv = x[b * NT + t];
    if (xv != 0) {
        g_c[gi] = cn;
        __nv_bfloat16 hi = __float2bfloat16(hn);
        g_Hs[b * RNN + hid] = hi;
        g_Hs[(b + 64) * RNN + hid] = __float2bfloat16(hn - __bfloat162float(hi));
    }
    if (xv == 2) g_pooled[gi] += hn;
}

// ---------------- head -----------------------------------------------------
__global__ __launch_bounds__(128) void head_kernel(const float* __restrict__ W1,
                                                   const float* __restrict__ b1,
                                                   const float* __restrict__ W2,
                                                   const float* __restrict__ b2,
                                                   const float* __restrict__ Wc,
                                                   const float* __restrict__ bc,
                                                   float* __restrict__ out) {
    const int b = blockIdx.x;
    const int tid = threadIdx.x;
    __shared__ float sp[RNN];
    __shared__ float h1s[HIDN];
    __shared__ float h2s[HIDN];
    __shared__ float lg[NLAB];

    for (int k = tid; k < RNN; k += 128) sp[k] = g_pooled[(size_t)b * RNN + k];
    __syncthreads();

    float a = b1[tid];
    for (int k = 0; k < RNN; k++) a += sp[k] * W1[(size_t)k * HIDN + tid];
    h1s[tid] = fmaxf(a, 0.f);
    __syncthreads();

    float a2 = b2[tid];
    for (int k = 0; k < HIDN; k++) a2 += h1s[k] * W2[(size_t)k * HIDN + tid];
    h2s[tid] = fmaxf(a2, 0.f);
    __syncthreads();

    if (tid < NLAB) {
        float l = bc[tid];
        for (int k = 0; k < HIDN; k++) l += h2s[k] * Wc[(size_t)k * NLAB + tid];
        lg[tid] = l;
    }
    __syncthreads();
    if (tid == 0) {
        const float mx = fmaxf(fmaxf(lg[0], lg[1]), fmaxf(lg[2], lg[3]));
        const float e0 = expf(lg[0] - mx), e1 = expf(lg[1] - mx);
        const float e2 = expf(lg[2] - mx), e3 = expf(lg[3] - mx);
        const float sden = e0 + e1 + e2 + e3;
        out[b * 4 + 0] = e0 / sden; out[b * 4 + 1] = e1 / sden;
        out[b * 4 + 2] = e2 / sden; out[b * 4 + 3] = e3 / sden;
    }
}

// ---------------- launcher -------------------------------------------------
extern "C" void kernel_launch(void* const* d_in, const int* in_sizes, int n_in,
                              void* d_out, int out_size) {
    const int*   x    = (const int*)d_in[0];
    const float* emb  = (const float*)d_in[1];
    const float* W    = (const float*)d_in[2];
    const float* U    = (const float*)d_in[3];
    const float* bias = (const float*)d_in[4];
    const float* W1   = (const float*)d_in[5];
    const float* b1   = (const float*)d_in[6];
    const float* W2   = (const float*)d_in[7];
    const float* b2   = (const float*)d_in[8];
    const float* Wc   = (const float*)d_in[9];
    const float* bc   = (const float*)d_in[10];
    float* out = (float*)d_out;

    cudaFuncSetAttribute(zgemm_kernel, cudaFuncAttributeMaxDynamicSharedMemorySize, GEMM_SMEM);
    cudaFuncSetAttribute(xw_mma_kernel, cudaFuncAttributeMaxDynamicSharedMemorySize, GEMM_SMEM);

    prep_kernel<<<1, 256>>>(x);
    zero_kernel<<<256, 256>>>();
    esplit_kernel<<<(VOCAB * EMBD) / 256, 256>>>(emb);
    upack_kernel<<<dim3(RNN / 64, Z4 / 64), 256>>>(U);
    wpack_kernel<<<dim3(EMBD / 64, Z4 / 64), 256>>>(W);
    xw_mma_kernel<<<dim3(32, NT), 256, GEMM_SMEM>>>(x);
    for (int t = 0; t < NT; t++) {
        zgemm_kernel<<<dim3(32, 2, 2), 256, GEMM_SMEM>>>(t);
        cell_kernel<<<256, 256>>>(x, bias, t);
    }
    head_kernel<<<NB, 128>>>(W1, b1, W2, b2, Wc, bc, out);
}